// round 11
// baseline (speedup 1.0000x reference)
#include <cuda_runtime.h>
#include <math.h>
#include <stdint.h>

#define NTOK 16384
#define HDIM 1024
#define NEXP 8
#define TOPK 2
#define FDIM 1024
#define BM 128
#define BK 32
#define NCH 32
#define RSTRIDE 36
#define TILEB (BM * RSTRIDE * 4)               // 18432 B
#define BUFB (2 * TILEB)
#define SMEM_GEMM (2 * BUFB)                   // 73728 B
#define NASSIGN (NTOK * TOPK)
#define PADDED_CAP (NASSIGN + NEXP * BM)       // 33792
#define ROWTILES (PADDED_CAP / BM)             // 264
#define NWEIGHT (NEXP * FDIM * HDIM)

// ---- scratch (static, no allocs) ----
__device__ __align__(1024) float g_xr[(size_t)NTOK * HDIM];
__device__ __align__(1024) float g_gater[(size_t)NWEIGHT];
__device__ __align__(1024) float g_upr[(size_t)NWEIGHT];
__device__ __align__(1024) float g_downr[(size_t)NWEIGHT];
__device__ __align__(1024) float g_hid[(size_t)PADDED_CAP * FDIM];
__device__ __align__(1024) float g_contrib[(size_t)PADDED_CAP * HDIM];
__device__ int   g_perm[PADDED_CAP];
__device__ float g_gw[PADDED_CAP];
__device__ int   g_rowof[NASSIGN];
__device__ int   g_tok_e[NASSIGN];
__device__ float g_tok_w[NASSIGN];
__device__ int   g_count[NEXP];
__device__ float g_usage[NEXP];
__device__ int   g_offset[NEXP + 1];

// ---- helpers ----
__device__ __forceinline__ void cp16(uint32_t d, const void* s) {
    asm volatile("cp.async.cg.shared.global [%0], [%1], 16;" :: "r"(d), "l"(s) : "memory");
}
__device__ __forceinline__ uint32_t smem_u32(const void* p) {
    uint32_t a;
    asm("{ .reg .u64 t; cvta.to.shared.u64 t, %1; cvt.u32.u64 %0, t; }" : "=r"(a) : "l"(p));
    return a;
}
#define CP_COMMIT() asm volatile("cp.async.commit_group;" ::: "memory")
#define CP_WAIT1()  asm volatile("cp.async.wait_group 1;" ::: "memory")
#define CP_WAIT0()  asm volatile("cp.async.wait_group 0;" ::: "memory")

__device__ __forceinline__ float rna_tf32(float v) {
    uint32_t r;
    asm("cvt.rna.tf32.f32 %0, %1;" : "=r"(r) : "f"(v));
    return __uint_as_float(r);
}
#define MMA8(c, a0, a1, a2, a3, b0, b1) \
    asm volatile("mma.sync.aligned.m16n8k8.row.col.f32.tf32.tf32.f32 " \
        "{%0,%1,%2,%3},{%4,%5,%6,%7},{%8,%9},{%0,%1,%2,%3};" \
        : "+f"((c)[0]), "+f"((c)[1]), "+f"((c)[2]), "+f"((c)[3]) \
        : "r"(a0), "r"(a1), "r"(a2), "r"(a3), "r"(b0), "r"(b1))
#define LDSM4(r0, r1, r2, r3, addr) \
    asm volatile("ldmatrix.sync.aligned.m8n8.x4.shared.b16 {%0,%1,%2,%3}, [%4];" \
        : "=r"(r0), "=r"(r1), "=r"(r2), "=r"(r3) : "r"(addr))

// ---- launch 1: fused tf32 rounding of x/gate/up/down + init ----
__global__ __launch_bounds__(256) void round_init_kernel(const float4* __restrict__ x,
                                                         const float4* __restrict__ gwp,
                                                         const float4* __restrict__ uwp,
                                                         const float4* __restrict__ dwp) {
    const int tid = blockIdx.x * blockDim.x + threadIdx.x;
    if (tid < PADDED_CAP) g_perm[tid] = -1;
    if (tid < NEXP) { g_count[tid] = 0; g_usage[tid] = 0.f; }
    const int NX4 = NTOK * HDIM / 4;
    const int NW4 = NWEIGHT / 4;
    const int total = NX4 + 3 * NW4;
    const int stride = gridDim.x * blockDim.x;
    for (int i = tid; i < total; i += stride) {
        const float4* s; float4* d; int j;
        if (i < NX4)                { s = x;   d = (float4*)g_xr;    j = i; }
        else if (i < NX4 + NW4)     { s = gwp; d = (float4*)g_gater; j = i - NX4; }
        else if (i < NX4 + 2 * NW4) { s = uwp; d = (float4*)g_upr;   j = i - NX4 - NW4; }
        else                        { s = dwp; d = (float4*)g_downr; j = i - NX4 - 2 * NW4; }
        float4 v = s[j];
        d[j] = make_float4(rna_tf32(v.x), rna_tf32(v.y), rna_tf32(v.z), rna_tf32(v.w));
    }
}

// ---- launch 2: router (exact fp32) ----
__global__ __launch_bounds__(128) void router_kernel(const float* __restrict__ x, const float* __restrict__ rw) {
    __shared__ float srw[NEXP * HDIM];
    __shared__ float sprob[NEXP];
    int tid = threadIdx.x;
    for (int i = tid; i < NEXP * HDIM; i += 128) srw[i] = rw[i];
    if (tid < NEXP) sprob[tid] = 0.f;
    __syncthreads();
    int warp = tid >> 5, lane = tid & 31;
    int t = blockIdx.x * 4 + warp;
    float acc[NEXP];
#pragma unroll
    for (int e = 0; e < NEXP; e++) acc[e] = 0.f;
    const float* xp = x + (size_t)t * HDIM;
    for (int j = lane; j < HDIM; j += 32) {
        float xv = xp[j];
#pragma unroll
        for (int e = 0; e < NEXP; e++) acc[e] += xv * srw[e * HDIM + j];
    }
#pragma unroll
    for (int e = 0; e < NEXP; e++)
#pragma unroll
        for (int o = 16; o; o >>= 1) acc[e] += __shfl_xor_sync(~0u, acc[e], o);
    if (lane == 0) {
        float mx = acc[0];
#pragma unroll
        for (int e = 1; e < NEXP; e++) mx = fmaxf(mx, acc[e]);
        float p[NEXP], s = 0.f;
#pragma unroll
        for (int e = 0; e < NEXP; e++) { p[e] = expf(acc[e] - mx); s += p[e]; }
        float inv = 1.f / s;
#pragma unroll
        for (int e = 0; e < NEXP; e++) p[e] *= inv;
        int e1 = 0;
#pragma unroll
        for (int e = 1; e < NEXP; e++) if (p[e] > p[e1]) e1 = e;
        int e2 = (e1 == 0) ? 1 : 0;
#pragma unroll
        for (int e = 0; e < NEXP; e++) if (e != e1 && p[e] > p[e2]) e2 = e;
        float ws = p[e1] + p[e2];
        g_tok_e[2 * t] = e1;     g_tok_w[2 * t] = p[e1] / ws;
        g_tok_e[2 * t + 1] = e2; g_tok_w[2 * t + 1] = p[e2] / ws;
        atomicAdd(&g_count[e1], 1);
        atomicAdd(&g_count[e2], 1);
#pragma unroll
        for (int e = 0; e < NEXP; e++) atomicAdd(&sprob[e], p[e]);
    }
    __syncthreads();
    if (tid < NEXP) atomicAdd(&g_usage[tid], sprob[tid]);
}

// ---- launch 3: scan + lb + placement (single block, smem cursors) ----
__global__ __launch_bounds__(256) void scan_place_kernel(float* lb_out, int wlb) {
    __shared__ int scur[NEXP];
    const int tid = threadIdx.x;
    if (tid == 0) {
        int off = 0;
        for (int e = 0; e < NEXP; e++) {
            g_offset[e] = off;
            off += ((g_count[e] + BM - 1) / BM) * BM;
        }
        g_offset[NEXP] = off;
        if (wlb) {
            float s = 0.f;
            for (int e = 0; e < NEXP; e++) { float u = g_usage[e] / (float)NTOK; s += u * u; }
            *lb_out = 0.01f * (float)NEXP * s;
        }
    }
    if (tid < NEXP) scur[tid] = 0;
    __syncthreads();
    for (int t = tid; t < NTOK; t += 256) {
#pragma unroll
        for (int k = 0; k < TOPK; k++) {
            int e = g_tok_e[2 * t + k];
            int pos = atomicAdd(&scur[e], 1);
            int row = g_offset[e] + pos;
            g_perm[row] = t;
            g_gw[row] = g_tok_w[2 * t + k];
            g_rowof[2 * t + k] = row;
        }
    }
}

// ==== launch 4: fused GEMM A: hid = rna(silu(X@gT) * (X@uT)) ====
// CTA 128 rows x 64 f; 4 warps, warp 64 rows x 32 f (gate+up). ldmatrix fragments.
__global__ __launch_bounds__(128, 2) void gemmA_fused() {
    extern __shared__ char smem[];
    __shared__ int toks[BM];
    const int tid = threadIdx.x;
    const int row0 = blockIdx.y * BM;
    if (row0 >= g_offset[NEXP]) return;
    const int f0 = blockIdx.x * 64;
    int e = 0;
    while (g_offset[e + 1] <= row0) e++;

    { int tk = g_perm[row0 + tid]; toks[tid] = tk < 0 ? 0 : tk; }
    __syncthreads();

    const uint32_t sbase = smem_u32(smem);
    const float* bg = g_gater + ((size_t)e * FDIM + f0) * 1024;
    const float* bu = g_upr   + ((size_t)e * FDIM + f0) * 1024;

    auto load_chunk = [&](int kc) {
        const int buf = kc & 1;
        const uint32_t sa = sbase + buf * BUFB;
        const uint32_t sb2 = sa + TILEB;
#pragma unroll
        for (int i = 0; i < 8; i++) {
            const int slot = tid + i * 128;
            const int row = slot >> 3, seg = slot & 7;
            cp16(sa + row * (RSTRIDE * 4) + seg * 16,
                 g_xr + (size_t)toks[row] * 1024 + kc * BK + seg * 4);
            const float* bs = (row < 64)
                ? bg + (size_t)row * 1024 + kc * BK + seg * 4
                : bu + (size_t)(row - 64) * 1024 + kc * BK + seg * 4;
            cp16(sb2 + row * (RSTRIDE * 4) + seg * 16, bs);
        }
        CP_COMMIT();
    };

    const int wid = tid >> 5, lane = tid & 31;
    const int wm = wid & 1, wn = wid >> 1;
    const int g = lane >> 2, tg = lane & 3;
    const int q = lane >> 3, r = lane & 7;
    // A LDSM: m0=(ar,klo) m1=(ar+8,klo) m2=(ar,khi) m3=(ar+8,khi)
    const uint32_t aOff = ((uint32_t)(wm * 64 + (q & 1) * 8 + r) * RSTRIDE + (q >> 1) * 4) * 4u;
    // B LDSM: m0=(br,klo) m1=(br,khi) m2=(br+8,klo) m3=(br+8,khi)
    const uint32_t bOff = ((uint32_t)(wn * 32 + (q >> 1) * 8 + r) * RSTRIDE + (q & 1) * 4) * 4u;

    float accg[4][4][4], accu[4][4][4];
#pragma unroll
    for (int i = 0; i < 4; i++)
#pragma unroll
        for (int j = 0; j < 4; j++)
#pragma unroll
            for (int k = 0; k < 4; k++) { accg[i][j][k] = 0.f; accu[i][j][k] = 0.f; }

    load_chunk(0);
    for (int kc = 0; kc < NCH; kc++) {
        if (kc + 1 < NCH) { load_chunk(kc + 1); CP_WAIT1(); }
        else              { CP_WAIT0(); }
        __syncthreads();
        const int buf = kc & 1;
        const uint32_t aA = sbase + buf * BUFB + aOff;
        const uint32_t bA = sbase + buf * BUFB + TILEB + bOff;
#pragma unroll
        for (int ks = 0; ks < 4; ks++) {
            uint32_t af[4][4], bfg[4][2], bfu[4][2];
#pragma unroll
            for (int mt = 0; mt < 4; mt++)
                LDSM4(af[mt][0], af[mt][1], af[mt][2], af[mt][3],
                      aA + mt * (16 * RSTRIDE * 4) + ks * 32);
#pragma unroll
            for (int np = 0; np < 2; np++) {
                LDSM4(bfg[2 * np][0], bfg[2 * np][1], bfg[2 * np + 1][0], bfg[2 * np + 1][1],
                      bA + np * (16 * RSTRIDE * 4) + ks * 32);
                LDSM4(bfu[2 * np][0], bfu[2 * np][1], bfu[2 * np + 1][0], bfu[2 * np + 1][1],
                      bA + (64 * RSTRIDE * 4) + np * (16 * RSTRIDE * 4) + ks * 32);
            }
#pragma unroll
            for (int mt = 0; mt < 4; mt++)
#pragma unroll
                for (int nt = 0; nt < 4; nt++) {
                    MMA8(accg[mt][nt], af[mt][0], af[mt][1], af[mt][2], af[mt][3],
                         bfg[nt][0], bfg[nt][1]);
                    MMA8(accu[mt][nt], af[mt][0], af[mt][1], af[mt][2], af[mt][3],
                         bfu[nt][0], bfu[nt][1]);
                }
        }
        __syncthreads();
    }

#pragma unroll
    for (int mt = 0; mt < 4; mt++) {
        const int r0 = row0 + wm * 64 + mt * 16 + g;
        const int r8 = r0 + 8;
#pragma unroll
        for (int nt = 0; nt < 4; nt++) {
            const int c = f0 + wn * 32 + nt * 8 + 2 * tg;
            float h0 = rna_tf32(__fdividef(accg[mt][nt][0], 1.f + __expf(-accg[mt][nt][0])) * accu[mt][nt][0]);
            float h1 = rna_tf32(__fdividef(accg[mt][nt][1], 1.f + __expf(-accg[mt][nt][1])) * accu[mt][nt][1]);
            float h2 = rna_tf32(__fdividef(accg[mt][nt][2], 1.f + __expf(-accg[mt][nt][2])) * accu[mt][nt][2]);
            float h3 = rna_tf32(__fdividef(accg[mt][nt][3], 1.f + __expf(-accg[mt][nt][3])) * accu[mt][nt][3]);
            *(float2*)(g_hid + (size_t)r0 * FDIM + c) = make_float2(h0, h1);
            *(float2*)(g_hid + (size_t)r8 * FDIM + c) = make_float2(h2, h3);
        }
    }
}

// ==== GEMM B: contrib = gw * (hid @ downT), CTA 128x128, warp 64x64 ====
__global__ __launch_bounds__(128, 2) void gemmB_kernel() {
    extern __shared__ char smem[];
    const int tid = threadIdx.x;
    const int row0 = blockIdx.y * BM;
    if (row0 >= g_offset[NEXP]) return;
    const int n0 = blockIdx.x * 128;
    int e = 0;
    while (g_offset[e + 1] <= row0) e++;

    const uint32_t sbase = smem_u32(smem);
    const float* bbase = g_downr + ((size_t)e * HDIM + n0) * 1024;

    auto load_chunk = [&](int kc) {
        const int buf = kc & 1;
        const uint32_t sa = sbase + buf * BUFB;
        const uint32_t sb2 = sa + TILEB;
#pragma unroll
        for (int i = 0; i < 8; i++) {
            const int slot = tid + i * 128;
            const int row = slot >> 3, seg = slot & 7;
            cp16(sa + row * (RSTRIDE * 4) + seg * 16,
                 g_hid + (size_t)(row0 + row) * 1024 + kc * BK + seg * 4);
            cp16(sb2 + row * (RSTRIDE * 4) + seg * 16,
                 bbase + (size_t)row * 1024 + kc * BK + seg * 4);
        }
        CP_COMMIT();
    };

    const int wid = tid >> 5, lane = tid & 31;
    const int wm = wid & 1, wn = wid >> 1;
    const int g = lane >> 2, tg = lane & 3;
    const int q = lane >> 3, r = lane & 7;
    const uint32_t aOff = ((uint32_t)(wm * 64 + (q & 1) * 8 + r) * RSTRIDE + (q >> 1) * 4) * 4u;
    const uint32_t bOff = ((uint32_t)(wn * 64 + (q >> 1) * 8 + r) * RSTRIDE + (q & 1) * 4) * 4u;

    float acc[4][8][4];
#pragma unroll
    for (int i = 0; i < 4; i++)
#pragma unroll
        for (int j = 0; j < 8; j++)
#pragma unroll
            for (int k = 0; k < 4; k++) acc[i][j][k] = 0.f;

    load_chunk(0);
    for (int kc = 0; kc < NCH; kc++) {
        if (kc + 1 < NCH) { load_chunk(kc + 1); CP_WAIT1(); }
        else              { CP_WAIT0(); }
        __syncthreads();
        const int buf = kc & 1;
        const uint32_t aA = sbase + buf * BUFB + aOff;
        const uint32_t bA = sbase + buf * BUFB + TILEB + bOff;
#pragma unroll
        for (int ks = 0; ks < 4; ks++) {
            uint32_t af[4][4], bf[8][2];
#pragma unroll
            for (int mt = 0; mt < 4; mt++)
                LDSM4(af[mt][0], af[mt][1], af[mt][2], af[mt][3],
                      aA + mt * (16 * RSTRIDE * 4) + ks * 32);
#pragma unroll
            for (int np = 0; np < 4; np++)
                LDSM4(bf[2 * np][0], bf[2 * np][1], bf[2 * np + 1][0], bf[2 * np + 1][1],
                      bA + np * (16 * RSTRIDE * 4) + ks * 32);
#pragma unroll
            for (int mt = 0; mt < 4; mt++)
#pragma unroll
                for (int nt = 0; nt < 8; nt++)
                    MMA8(acc[mt][nt], af[mt][0], af[mt][1], af[mt][2], af[mt][3],
                         bf[nt][0], bf[nt][1]);
        }
        __syncthreads();
    }

#pragma unroll
    for (int mt = 0; mt < 4; mt++) {
        const int r0 = row0 + wm * 64 + mt * 16 + g;
        const int r8 = r0 + 8;
        const float w0 = g_gw[r0], w8 = g_gw[r8];
#pragma unroll
        for (int nt = 0; nt < 8; nt++) {
            const int c = n0 + wn * 64 + nt * 8 + 2 * tg;
            *(float2*)(g_contrib + (size_t)r0 * HDIM + c) =
                make_float2(acc[mt][nt][0] * w0, acc[mt][nt][1] * w0);
            *(float2*)(g_contrib + (size_t)r8 * HDIM + c) =
                make_float2(acc[mt][nt][2] * w8, acc[mt][nt][3] * w8);
        }
    }
}

// ---- combine (deterministic) ----
__global__ void combine_kernel(float* __restrict__ out) {
    int idx = blockIdx.x * blockDim.x + threadIdx.x;
    if (idx >= NTOK * (HDIM / 4)) return;
    int n = idx >> 8;
    int hq = (idx & 255) * 4;
    int r0 = g_rowof[2 * n], r1 = g_rowof[2 * n + 1];
    float4 a = *(const float4*)&g_contrib[(size_t)r0 * HDIM + hq];
    float4 b = *(const float4*)&g_contrib[(size_t)r1 * HDIM + hq];
    *(float4*)&out[(size_t)n * HDIM + hq] =
        make_float4(a.x + b.x, a.y + b.y, a.z + b.z, a.w + b.w);
}

// ---- launch ----
extern "C" void kernel_launch(void* const* d_in, const int* in_sizes, int n_in,
                              void* d_out, int out_size) {
    const float* x  = (const float*)d_in[0];
    const float* rw = (const float*)d_in[1];
    const float* gw = (const float*)d_in[2];
    const float* uw = (const float*)d_in[3];
    const float* dw = (const float*)d_in[4];
    float* out = (float*)d_out;
    int wlb = (out_size > NTOK * HDIM) ? 1 : 0;
    float* lb_ptr = out + (size_t)NTOK * HDIM;

    cudaFuncSetAttribute(gemmA_fused, cudaFuncAttributeMaxDynamicSharedMemorySize, SMEM_GEMM);
    cudaFuncSetAttribute(gemmB_kernel, cudaFuncAttributeMaxDynamicSharedMemorySize, SMEM_GEMM);

    round_init_kernel<<<2048, 256>>>((const float4*)x, (const float4*)gw,
                                     (const float4*)uw, (const float4*)dw);
    router_kernel<<<NTOK / 4, 128>>>(x, rw);
    scan_place_kernel<<<1, 256>>>(lb_ptr, wlb);

    dim3 gA(FDIM / 64, ROWTILES);                    // (16, 264)
    gemmA_fused<<<gA, 128, SMEM_GEMM>>>();
    dim3 gB(HDIM / 128, ROWTILES);                   // (8, 264)
    gemmB_kernel<<<gB, 128, SMEM_GEMM>>>();

    combine_kernel<<<(NTOK * (HDIM / 4) + 255) / 256, 256>>>(out);
}